// round 16
// baseline (speedup 1.0000x reference)
#include <cuda_runtime.h>
#include <math.h>

#define LAM 1.0
#define NT 128
#define FULLM 0xffffffffu

// Single-warp banded Schur (generator) Toeplitz Cholesky fused with
// y = L @ (sqrt(D) z), zero barriers in the main recursion.
//
// Software-pipelined: the pivot SHFL.IDX, ring SHFL, and the noise LDS.128
// for step n+1 are issued at the END of step n, overlapping their latency
// with step n's rotation FMAs. Per-step critical chain is then just
// fma -> rsqrt -> mul -> rotation FMAs.
//
// Row idx = lane*4 + slot (128-row sliding window; covariance truncated at
// lag 128, error ~1e-26). v[j], y[j] are row-stationary registers; u[lag]
// hands to the next row via 3 renames + 1 ring shuffle. Diagonal
// finalization is branch-free (SEL'd STS.128 to dx or per-lane scratch).
__global__ __launch_bounds__(NT, 1)
void fbm_warp_pipe(const float* __restrict__ alpha,
                   const float* __restrict__ tau,
                   const float* __restrict__ diff,
                   const float* __restrict__ du,
                   float* __restrict__ out,
                   int T)
{
    const int N = T - 1;                       // 1023
    extern __shared__ float sh[];
    float*  rsh  = sh;                         // [128]  truncated autocovariance
    float4* w4   = (float4*)(sh + 128);        // [N+1]  scaled noise (padded)
    float4* dx4  = w4 + (N + 1);               // [N]    finalized increments
    float4* scr4 = dx4 + N;                    // [32]   per-lane dump target

    const int b   = blockIdx.x;
    const int tid = threadIdx.x;

    const double a  = (double)alpha[b];
    const float  tb = tau[b];
    const float  sd = sqrtf(diff[b]);

    // ---- prologue: r[0..127] (fp64), stage noise as float4 ----
    if (tid < 128) {
        int k = tid;
        double kp = pow((double)(k + 1), a);
        double km = (k == 1) ? 0.0 : pow((double)(k >= 1 ? k - 1 : 1 - k), a);
        double k0 = (k == 0) ? 0.0 : pow((double)k, a);
        double R  = 0.5 * (kp + km - 2.0 * k0);
        if ((float)k >= tb) R *= exp(-LAM * (double)((float)k - tb));
        rsh[k] = (float)R;                     // r[0] == 1 exactly
    }
    const float* dub = du + (size_t)b * N * 3;
    for (int k = tid; k < N; k += NT) {
        float4 t4;
        t4.x = dub[3 * k]     * sd;
        t4.y = dub[3 * k + 1] * sd;
        t4.z = dub[3 * k + 2] * sd;
        t4.w = 0.f;
        w4[k] = t4;
    }
    if (tid == 0) w4[N] = make_float4(0.f, 0.f, 0.f, 0.f);   // prefetch pad
    __syncthreads();

    if (tid < 32) {
        const int lane = tid;
        const int src  = (lane + 31) & 31;     // ring: lane <- lane-1 (mod 32)

        float uo[4], vv[4], y[4][3];
        const float4 w0 = w4[0];
        #pragma unroll
        for (int s = 0; s < 4; s++) {
            float rv = rsh[lane * 4 + s];
            uo[s] = rv; vv[s] = rv;
            y[s][0] = rv * w0.x; y[s][1] = rv * w0.y; y[s][2] = rv * w0.z;
        }
        if (lane == 0) {                        // row 0 finalizes at n=0
            vv[0] = 0.f; uo[0] = 0.f;
            y[0][0] = y[0][1] = y[0][2] = 0.f;
            float4 q; q.x = w0.x; q.y = w0.y; q.z = w0.z; q.w = 0.f;
            dx4[0] = q;
        }

        float u0 = 1.f, u0sq = 1.f;
        int n = 1;

        // prime the pipeline for n = 1 (S=1, lane_sel=0)
        float4 wn   = w4[1];
        float  vnp  = __shfl_sync(FULLM, vv[1], 0);
        float  ring = __shfl_sync(FULLM, uo[3], src);

        #define ROTS(s_, inu_) {                                          \
            float un_ = fmaf(c_, (inu_), cr_ * vv[s_]);                   \
            vv[s_]   = fmaf(c_, vv[s_], cr_ * (inu_));                    \
            uo[s_]   = un_;                                               \
            y[s_][0] = fmaf(un_, wn.x, y[s_][0]);                         \
            y[s_][1] = fmaf(un_, wn.y, y[s_][1]);                         \
            y[s_][2] = fmaf(un_, wn.z, y[s_][2]); }

        #define ROTD(s_, inu_) {                                          \
            float un_ = fmaf(c_, (inu_), cr_ * vv[s_]);                   \
            float vn_ = fmaf(c_, vv[s_], cr_ * (inu_));                   \
            bool  p_  = (lane == lane_sel);                               \
            float cf_ = p_ ? u0n_ : un_;                                  \
            float f0_ = fmaf(cf_, wn.x, y[s_][0]);                        \
            float f1_ = fmaf(cf_, wn.y, y[s_][1]);                        \
            float f2_ = fmaf(cf_, wn.z, y[s_][2]);                        \
            float4* ad_ = p_ ? (dx4 + n) : (scr4 + lane);                 \
            float4 q_; q_.x = f0_; q_.y = f1_; q_.z = f2_; q_.w = 0.f;    \
            *ad_ = q_;                                                    \
            y[s_][0] = p_ ? 0.f : f0_;                                    \
            y[s_][1] = p_ ? 0.f : f1_;                                    \
            y[s_][2] = p_ ? 0.f : f2_;                                    \
            vv[s_] = p_ ? 0.f : vn_;                                      \
            uo[s_] = p_ ? 0.f : un_; }

        // pipelined body: consumes prefetched {vnp, ring, wn}; prefetches next
        #define BODY(S_, SN_) {                                           \
            const int lane_sel = (n & 127) >> 2;                          \
            const float t_ = fmaf(-vnp, vnp, u0sq);                       \
            const float s_ = rsqrtf(t_);                                  \
            const float c_ = u0 * s_;                                     \
            const float cr_ = -vnp * s_;                                  \
            const float u0n_ = t_ * s_;                                   \
            u0 = u0n_; u0sq = t_;                                         \
            const float in3 = uo[2], in2 = uo[1], in1 = uo[0], in0 = ring;\
            if (S_ == 3) { ROTD(3, in3) } else { ROTS(3, in3) }           \
            if (S_ == 2) { ROTD(2, in2) } else { ROTS(2, in2) }           \
            if (S_ == 1) { ROTD(1, in1) } else { ROTS(1, in1) }           \
            if (S_ == 0) { ROTD(0, in0) } else { ROTS(0, in0) }           \
            n++;                                                          \
            wn   = w4[n];                                                 \
            vnp  = __shfl_sync(FULLM, vv[SN_], (n & 127) >> 2);           \
            ring = __shfl_sync(FULLM, uo[3], src); }

        // main: 4x unrolled, slot index compile-time (n starts at 1)
        while (n <= N - 4) { BODY(1, 2) BODY(2, 3) BODY(3, 0) BODY(0, 1) }
        // tail (<= 3 steps): runtime slot select, self-contained
        while (n <= N - 1) {
            const int S_ = n & 3;
            const int lane_sel = (n & 127) >> 2;
            const float4 wt = w4[n];
            float pvv = (S_ == 0) ? vv[0] : (S_ == 1) ? vv[1]
                      : (S_ == 2) ? vv[2] : vv[3];
            const float vt   = __shfl_sync(FULLM, pvv, lane_sel);
            const float rg   = __shfl_sync(FULLM, uo[3], src);
            const float t_ = fmaf(-vt, vt, u0sq);
            const float s_ = rsqrtf(t_);
            const float c_ = u0 * s_;
            const float cr_ = -vt * s_;
            const float u0n_ = t_ * s_;
            u0 = u0n_; u0sq = t_;
            const float in[4] = { rg, uo[0], uo[1], uo[2] };
            #pragma unroll
            for (int s2 = 0; s2 < 4; s2++) {
                float un_ = fmaf(c_, in[s2], cr_ * vv[s2]);
                float vn_ = fmaf(c_, vv[s2], cr_ * in[s2]);
                bool  p_  = (s2 == S_) && (lane == lane_sel);
                float cf_ = p_ ? u0n_ : un_;
                float f0_ = fmaf(cf_, wt.x, y[s2][0]);
                float f1_ = fmaf(cf_, wt.y, y[s2][1]);
                float f2_ = fmaf(cf_, wt.z, y[s2][2]);
                float4* ad_ = p_ ? (dx4 + n) : (scr4 + lane);
                float4 q_; q_.x = f0_; q_.y = f1_; q_.z = f2_; q_.w = 0.f;
                *ad_ = q_;
                y[s2][0] = p_ ? 0.f : f0_;
                y[s2][1] = p_ ? 0.f : f1_;
                y[s2][2] = p_ ? 0.f : f2_;
                vv[s2] = p_ ? 0.f : vn_;
                uo[s2] = p_ ? 0.f : un_;
            }
            n++;
        }
        #undef BODY
        #undef ROTD
        #undef ROTS
    }
    __syncthreads();

    // ---- cumsum per dim: warp d scans component d of dx4 ----
    {
        int warp = tid >> 5, lane = tid & 31;
        if (warp < 3) {
            float* base = (float*)dx4 + warp;    // stride-4 plane
            int chunk = (N + 31) >> 5;
            int lo = lane * chunk;
            int hi = lo + chunk; if (hi > N) hi = N;
            float run = 0.f;
            for (int k = lo; k < hi; k++) { run += base[4 * k]; base[4 * k] = run; }
            float tot = run;
            #pragma unroll
            for (int o = 1; o < 32; o <<= 1) {
                float t2 = __shfl_up_sync(FULLM, tot, o);
                if (lane >= o) tot += t2;
            }
            float off = tot - run;               // exclusive prefix of chunk sums
            for (int k = lo; k < hi; k++) base[4 * k] += off;
        }
    }
    __syncthreads();

    // ---- output: leading zero row + interleaved dims, coalesced ----
    float* ob = out + (size_t)b * T * 3;
    for (int idx = tid; idx < T * 3; idx += NT) {
        int t = idx / 3, d = idx - 3 * t;
        float val = 0.f;
        if (t > 0) val = ((float*)(dx4 + (t - 1)))[d];
        ob[idx] = val;
    }
}

extern "C" void kernel_launch(void* const* d_in, const int* in_sizes, int n_in,
                              void* d_out, int out_size)
{
    const float* alpha = (const float*)d_in[0];
    const float* tau   = (const float*)d_in[1];
    const float* diffu = (const float*)d_in[2];
    const float* du    = (const float*)d_in[3];
    float* out = (float*)d_out;

    const int BS   = in_sizes[0];
    const int duN  = in_sizes[3] / BS;   // (T-1)*dim
    const int outN = out_size / BS;      // T*dim
    const int dim  = outN - duN;         // 3
    const int T    = outN / dim;
    const int N    = T - 1;

    size_t smem = (size_t)(128 + 4 * (N + 1) + 4 * N + 4 * 32) * sizeof(float);

    cudaFuncSetAttribute(fbm_warp_pipe,
                         cudaFuncAttributeMaxDynamicSharedMemorySize, (int)smem);

    fbm_warp_pipe<<<BS, NT, smem>>>(alpha, tau, diffu, du, out, T);
}